// round 10
// baseline (speedup 1.0000x reference)
#include <cuda_runtime.h>
#include <cuda_bf16.h>
#include <cstdint>

// Problem constants
#define BB   8
#define TT   2048
#define DD   1024
#define HH   64
#define MTOT (BB * TT)   // 16384

// Pre-split (hi/lo bf16) Q,K,V produced by the projection kernel. Q pre-scaled 1/8.
__device__ __nv_bfloat16 g_qH[(size_t)MTOT * HH];
__device__ __nv_bfloat16 g_qL[(size_t)MTOT * HH];
__device__ __nv_bfloat16 g_kH[(size_t)MTOT * HH];
__device__ __nv_bfloat16 g_kL[(size_t)MTOT * HH];
__device__ __nv_bfloat16 g_vH[(size_t)MTOT * HH];
__device__ __nv_bfloat16 g_vL[(size_t)MTOT * HH];
// Split-precision transposed weights
__device__ __nv_bfloat16 g_WtH[192 * 1024];
__device__ __nv_bfloat16 g_WtL[192 * 1024];

// ===========================================================================
// Helpers (plain sm_100-compatible: mma.sync + cp.async + ldmatrix)
// ===========================================================================
__device__ __forceinline__ uint32_t smem_u32(const void* p) {
    uint32_t a;
    asm("{ .reg .u64 t; cvta.to.shared.u64 t, %1; cvt.u32.u64 %0, t; }"
        : "=r"(a) : "l"(p));
    return a;
}
#define CP_ASYNC16(dst, src) \
    asm volatile("cp.async.cg.shared.global [%0], [%1], 16;" \
                 :: "r"(dst), "l"(src) : "memory")
#define CP_COMMIT() asm volatile("cp.async.commit_group;" ::: "memory")
#define CP_WAIT1()  asm volatile("cp.async.wait_group 1;" ::: "memory")
#define CP_WAIT0()  asm volatile("cp.async.wait_group 0;" ::: "memory")

// split one float2 into packed bf16x2 hi and residual-lo fragments
__device__ __forceinline__ void split2(float2 f, uint32_t& hi, uint32_t& lo) {
    uint32_t h;
    asm("cvt.rn.bf16x2.f32 %0, %1, %2;" : "=r"(h) : "f"(f.y), "f"(f.x));
    float hf0 = __uint_as_float(h << 16);
    float hf1 = __uint_as_float(h & 0xffff0000u);
    float l0 = f.x - hf0;
    float l1 = f.y - hf1;
    asm("cvt.rn.bf16x2.f32 %0, %1, %2;" : "=r"(lo) : "f"(l1), "f"(l0));
    hi = h;
}

__device__ __forceinline__ void mma16816(float* c, const uint32_t* a, uint2 b) {
    asm volatile(
        "mma.sync.aligned.m16n8k16.row.col.f32.bf16.bf16.f32 "
        "{%0,%1,%2,%3}, {%4,%5,%6,%7}, {%8,%9}, {%0,%1,%2,%3};"
        : "+f"(c[0]), "+f"(c[1]), "+f"(c[2]), "+f"(c[3])
        : "r"(a[0]), "r"(a[1]), "r"(a[2]), "r"(a[3]), "r"(b.x), "r"(b.y));
}

__device__ __forceinline__ void ldmx4t(uint32_t* r, uint32_t addr) {
    asm volatile("ldmatrix.sync.aligned.m8n8.x4.trans.shared.b16 "
                 "{%0,%1,%2,%3}, [%4];"
                 : "=r"(r[0]), "=r"(r[1]), "=r"(r[2]), "=r"(r[3]) : "r"(addr));
}
__device__ __forceinline__ void ldmx4(uint32_t* r, uint32_t addr) {
    asm volatile("ldmatrix.sync.aligned.m8n8.x4.shared.b16 "
                 "{%0,%1,%2,%3}, [%4];"
                 : "=r"(r[0]), "=r"(r[1]), "=r"(r[2]), "=r"(r[3]) : "r"(addr));
}

// ===========================================================================
// Kernel 0: W prep (unchanged, passing).
// ===========================================================================
__global__ __launch_bounds__(256) void wprep_kernel(
    const float* __restrict__ Wq,
    const float* __restrict__ Wk,
    const float* __restrict__ Wv)
{
    const int n = blockIdx.x;                 // 0..191
    const float* W = (n < 64) ? Wq : ((n < 128) ? Wk : Wv);
    const int nn = n & 63;
    for (int k = threadIdx.x; k < 1024; k += 256) {
        float w = W[(size_t)k * 64 + nn];
        __nv_bfloat16 h = __float2bfloat16(w);
        float r = w - __bfloat162float(h);
        int p   = (k & 15) >> 1;
        int pos = (k & ~15) + (p & 3) * 4 + (p >> 2) * 2 + (k & 1);
        g_WtH[(size_t)n * 1024 + pos] = h;
        g_WtL[(size_t)n * 1024 + pos] = __float2bfloat16(r);
    }
}

// ===========================================================================
// Kernel 1: QKV projection via mma.sync bf16 split precision (unchanged).
// Epilogue emits pre-split hi/lo bf16 (Q scaled 1/8).
// ===========================================================================
#define XS_STRIDE 272
#define WS_STRIDE 144
#define XS_BYTES  (128 * XS_STRIDE)
#define WS_BYTES  (192 * WS_STRIDE)
#define QS_STAGE  (XS_BYTES + 2 * WS_BYTES)
#define QS_TOTAL  (2 * QS_STAGE)

__global__ __launch_bounds__(256, 1) void qkv_mma_kernel(const float* __restrict__ X)
{
    extern __shared__ char smem[];
    const uint32_t sb = smem_u32(smem);
    const int tid  = threadIdx.x;
    const int wid  = tid >> 5;
    const int lane = tid & 31;
    const int gid  = lane >> 2;
    const int tq   = lane & 3;
    const int wm   = (wid & 3) * 32;
    const int wn   = (wid >> 2) * 96;

    const char* Xg = (const char*)(X + (size_t)blockIdx.x * 128 * DD);
    const char* WHg = (const char*)g_WtH;
    const char* WLg = (const char*)g_WtL;

    auto issue = [&](int c, int s) {
        const uint32_t st = sb + s * QS_STAGE;
        const char* xs = Xg + c * 256;
#pragma unroll
        for (int i = 0; i < 8; i++) {
            int u = tid + 256 * i;
            int r = u >> 4, col = u & 15;
            CP_ASYNC16(st + r * XS_STRIDE + col * 16, xs + (size_t)r * 4096 + col * 16);
        }
        const uint32_t wh = st + XS_BYTES;
        const uint32_t wl = wh + WS_BYTES;
        const char* whs = WHg + c * 128;
        const char* wls = WLg + c * 128;
#pragma unroll
        for (int i = 0; i < 6; i++) {
            int u = tid + 256 * i;
            int n = u >> 3, col = u & 7;
            CP_ASYNC16(wh + n * WS_STRIDE + col * 16, whs + (size_t)n * 2048 + col * 16);
            CP_ASYNC16(wl + n * WS_STRIDE + col * 16, wls + (size_t)n * 2048 + col * 16);
        }
        CP_COMMIT();
    };

    float acc[2][12][4];
#pragma unroll
    for (int m = 0; m < 2; m++)
#pragma unroll
        for (int j = 0; j < 12; j++) {
            acc[m][j][0] = 0.f; acc[m][j][1] = 0.f;
            acc[m][j][2] = 0.f; acc[m][j][3] = 0.f;
        }

    issue(0, 0);

    for (int c = 0; c < 16; c++) {
        const int s = c & 1;
        if (c < 15) { issue(c + 1, s ^ 1); CP_WAIT1(); }
        else        { CP_WAIT0(); }
        __syncthreads();

        const char* Xs = smem + s * QS_STAGE;
        const char* Wh = Xs + XS_BYTES;
        const char* Wl = Wh + WS_BYTES;

#pragma unroll
        for (int ks = 0; ks < 4; ks++) {
            uint32_t Ah[2][4], Al[2][4];
#pragma unroll
            for (int m = 0; m < 2; m++) {
                const int r0 = wm + m * 16 + gid;
                const char* base = Xs + (size_t)r0 * XS_STRIDE + ks * 64 + tq * 8;
                float2 f0 = *(const float2*)(base);
                float2 f1 = *(const float2*)(base + 8 * XS_STRIDE);
                float2 f2 = *(const float2*)(base + 32);
                float2 f3 = *(const float2*)(base + 8 * XS_STRIDE + 32);
                split2(f0, Ah[m][0], Al[m][0]);
                split2(f1, Ah[m][1], Al[m][1]);
                split2(f2, Ah[m][2], Al[m][2]);
                split2(f3, Ah[m][3], Al[m][3]);
            }
#pragma unroll
            for (int j = 0; j < 12; j++) {
                const size_t boff = (size_t)(wn + j * 8 + gid) * WS_STRIDE + ks * 32 + tq * 8;
                uint2 bh = *(const uint2*)(Wh + boff);
                uint2 bl = *(const uint2*)(Wl + boff);
#pragma unroll
                for (int m = 0; m < 2; m++) {
                    mma16816(acc[m][j], Ah[m], bh);
                    mma16816(acc[m][j], Ah[m], bl);
                    mma16816(acc[m][j], Al[m], bh);
                }
            }
        }
        __syncthreads();
    }

    // ---- epilogue: split to hi/lo bf16 and store (Q pre-scaled by 1/8) ----
#pragma unroll
    for (int m = 0; m < 2; m++) {
        const size_t row = (size_t)blockIdx.x * 128 + wm + m * 16 + gid;
#pragma unroll
        for (int j = 0; j < 12; j++) {
            const int nc = wn + j * 8 + tq * 2;
            const int g  = nc >> 6;
            const int cc = nc & 63;
            const float sc = (g == 0) ? 0.125f : 1.0f;
            __nv_bfloat16* H = (g == 0) ? g_qH : ((g == 1) ? g_kH : g_vH);
            __nv_bfloat16* L = (g == 0) ? g_qL : ((g == 1) ? g_kL : g_vL);
            uint32_t h0, l0, h1, l1;
            split2(make_float2(acc[m][j][0] * sc, acc[m][j][1] * sc), h0, l0);
            split2(make_float2(acc[m][j][2] * sc, acc[m][j][3] * sc), h1, l1);
            *(uint32_t*)((char*)H + (row * HH + cc) * 2)       = h0;
            *(uint32_t*)((char*)L + (row * HH + cc) * 2)       = l0;
            *(uint32_t*)((char*)H + ((row + 8) * HH + cc) * 2) = h1;
            *(uint32_t*)((char*)L + ((row + 8) * HH + cc) * 2) = l1;
        }
    }
}

// ===========================================================================
// Kernel 2: flash attention (causal) — split bf16 mma.sync, 16 WARPS/CTA.
// 512 threads: 4 kv-col-quarter groups (ch) x 4 q-row groups (rg).
// Per warp/iter: 24 S-MMAs + 24 PV-MMAs. O partials reduced 4-way at epilogue.
// q-tile 64, kv-tile 64, pairing {g, 31-g} -> 33 iters/block, 128 blocks.
// ===========================================================================
#define ASTR      144        // smem tile row stride (64*2 bf16 + 16 pad)
#define SM_QH     0
#define SM_QL     9216
#define SM_KV     18432
#define KV_STAGE  36864      // KH, KL, VH, VL at +0, +9216, +18432, +27648
#define SM_RA     92160      // float[4][64]
#define SM_RB     93184      // float[4][64]
#define SM_OB     18432      // epilogue O buffers (overlap KV stages)
#define ATTN_SMEM 94208

__global__ __launch_bounds__(512, 1) void attn_kernel(float* __restrict__ Out)
{
    extern __shared__ char smem[];
    const uint32_t sb = smem_u32(smem);

    const int b = blockIdx.y;
    const int g = blockIdx.x;
    const int tid  = threadIdx.x;
    const int wid  = tid >> 5;
    const int lane = tid & 31;
    const int ch   = wid >> 2;     // kv col quarter (16 cols each)
    const int rg   = wid & 3;      // q row group (16 rows)
    const int gid  = lane >> 2;
    const int tq   = lane & 3;

    const size_t boff = (size_t)b * TT * HH * 2;   // byte offset for this batch
    const char* qHg = (const char*)g_qH + boff;
    const char* qLg = (const char*)g_qL + boff;
    const char* kHg = (const char*)g_kH + boff;
    const char* kLg = (const char*)g_kL + boff;
    const char* vHg = (const char*)g_vH + boff;
    const char* vLg = (const char*)g_vL + boff;

    float* redA = (float*)(smem + SM_RA);   // [4][64] maxima
    float* redB = (float*)(smem + SM_RB);   // [4][64] sums

    const int r0 = 16 * rg + gid;       // this thread's q rows (local)
    const int r1 = r0 + 8;

    // ldmatrix lane address components
    const int lrow = (lane & 7) + ((lane >> 3) & 1) * 8;   // for trans V loads
    const int lcol = (lane >> 4) * 8;
    const uint32_t kml = (uint32_t)((lane & 7) * ASTR + (lane >> 3) * 16); // K ldmx

    // async loaders -------------------------------------------------------
    auto issue_q = [&](int q0) {
#pragma unroll
        for (int i = 0; i < 2; i++) {
            int u = tid + 512 * i;             // 0..1023
            int t = u >> 9;                    // 0: H, 1: L
            int r = (u >> 3) & 63;
            int cc = u & 7;
            const char* src = (t ? qLg : qHg) + (size_t)(q0 + r) * 128 + cc * 16;
            CP_ASYNC16(sb + SM_QH + t * 9216 + r * ASTR + cc * 16, src);
        }
        CP_COMMIT();
    };
    auto issue_kv = [&](int k0, int s) {
        const uint32_t base = sb + SM_KV + s * KV_STAGE;
#pragma unroll
        for (int i = 0; i < 4; i++) {
            int u = tid + 512 * i;             // 0..2047
            int t = u >> 9;                    // 0..3 -> KH,KL,VH,VL
            int r = (u >> 3) & 63;
            int cc = u & 7;
            const char* src = (t == 0 ? kHg : t == 1 ? kLg : t == 2 ? vHg : vLg)
                              + (size_t)(k0 + r) * 128 + cc * 16;
            CP_ASYNC16(base + t * 9216 + r * ASTR + cc * 16, src);
        }
        CP_COMMIT();
    };

    for (int pi = 0; pi < 2; pi++) {
        const int qt = pi ? (31 - g) : g;
        const int q0 = qt * 64;

        issue_q(q0);
        issue_kv(0, 0);

        float m0 = -1e20f, m1 = -1e20f, l0 = 0.f, l1 = 0.f;
        float oacc[8][4];
#pragma unroll
        for (int j = 0; j < 8; j++) {
            oacc[j][0] = 0.f; oacc[j][1] = 0.f; oacc[j][2] = 0.f; oacc[j][3] = 0.f;
        }

        for (int kt = 0; kt <= qt; kt++) {
            CP_WAIT0();
            __syncthreads();
            if (kt < qt) issue_kv((kt + 1) * 64, (kt + 1) & 1);

            const uint32_t stg = sb + SM_KV + (kt & 1) * KV_STAGE;

            // ---- S = Q @ K^T over this warp's 16 kv cols ----
            float sacc[2][4];
            sacc[0][0] = 0.f; sacc[0][1] = 0.f; sacc[0][2] = 0.f; sacc[0][3] = 0.f;
            sacc[1][0] = 0.f; sacc[1][1] = 0.f; sacc[1][2] = 0.f; sacc[1][3] = 0.f;
            {
                const char* qh = smem + SM_QH + r0 * ASTR + tq * 4;
                const char* ql = qh + 9216;
#pragma unroll
                for (int kbp = 0; kbp < 2; kbp++) {
                    // Q fragments for k16 blocks 2*kbp, 2*kbp+1
                    uint32_t Ah[2][4], Al[2][4];
#pragma unroll
                    for (int q = 0; q < 2; q++) {
                        const int kb = 2 * kbp + q;
                        Ah[q][0] = *(const uint32_t*)(qh + kb * 32);
                        Ah[q][1] = *(const uint32_t*)(qh + 8 * ASTR + kb * 32);
                        Ah[q][2] = *(const uint32_t*)(qh + kb * 32 + 16);
                        Ah[q][3] = *(const uint32_t*)(qh + 8 * ASTR + kb * 32 + 16);
                        Al[q][0] = *(const uint32_t*)(ql + kb * 32);
                        Al[q][1] = *(const uint32_t*)(ql + 8 * ASTR + kb * 32);
                        Al[q][2] = *(const uint32_t*)(ql + kb * 32 + 16);
                        Al[q][3] = *(const uint32_t*)(ql + 8 * ASTR + kb * 32 + 16);
                    }
#pragma unroll
                    for (int j = 0; j < 2; j++) {
                        const uint32_t kbase =
                            stg + (uint32_t)((16 * ch + 8 * j) * ASTR) + kml + kbp * 64;
                        uint32_t KH[4], KL[4];
                        ldmx4(KH, kbase);
                        ldmx4(KL, kbase + 9216);
                        mma16816(sacc[j], Ah[0], make_uint2(KH[0], KH[1]));
                        mma16816(sacc[j], Ah[1], make_uint2(KH[2], KH[3]));
                        mma16816(sacc[j], Ah[0], make_uint2(KL[0], KL[1]));
                        mma16816(sacc[j], Ah[1], make_uint2(KL[2], KL[3]));
                        mma16816(sacc[j], Al[0], make_uint2(KH[0], KH[1]));
                        mma16816(sacc[j], Al[1], make_uint2(KH[2], KH[3]));
                    }
                }
            }

            // ---- causal mask + local (quarter-width) max ----
            const bool diag = (kt == qt);
            float mx0 = -1e30f, mx1 = -1e30f;
#pragma unroll
            for (int j = 0; j < 2; j++) {
                const int c0 = 16 * ch + 8 * j + 2 * tq;
                if (diag) {
                    if (c0     > r0) sacc[j][0] = -1e30f;
                    if (c0 + 1 > r0) sacc[j][1] = -1e30f;
                    if (c0     > r1) sacc[j][2] = -1e30f;
                    if (c0 + 1 > r1) sacc[j][3] = -1e30f;
                }
                mx0 = fmaxf(mx0, fmaxf(sacc[j][0], sacc[j][1]));
                mx1 = fmaxf(mx1, fmaxf(sacc[j][2], sacc[j][3]));
            }
            mx0 = fmaxf(mx0, __shfl_xor_sync(0xffffffffu, mx0, 1));
            mx0 = fmaxf(mx0, __shfl_xor_sync(0xffffffffu, mx0, 2));
            mx1 = fmaxf(mx1, __shfl_xor_sync(0xffffffffu, mx1, 1));
            mx1 = fmaxf(mx1, __shfl_xor_sync(0xffffffffu, mx1, 2));
            mx0 = fmaxf(mx0, -1e20f);   // clamp: fully-masked quarter -> zeros
            mx1 = fmaxf(mx1, -1e20f);

            // exp against LOCAL max + local sums
            float s0 = 0.f, s1 = 0.f;
#pragma unroll
            for (int j = 0; j < 2; j++) {
                sacc[j][0] = __expf(sacc[j][0] - mx0);
                sacc[j][1] = __expf(sacc[j][1] - mx0);
                sacc[j][2] = __expf(sacc[j][2] - mx1);
                sacc[j][3] = __expf(sacc[j][3] - mx1);
                s0 += sacc[j][0] + sacc[j][1];
                s1 += sacc[j][2] + sacc[j][3];
            }
            s0 += __shfl_xor_sync(0xffffffffu, s0, 1);
            s0 += __shfl_xor_sync(0xffffffffu, s0, 2);
            s1 += __shfl_xor_sync(0xffffffffu, s1, 1);
            s1 += __shfl_xor_sync(0xffffffffu, s1, 2);

            // ---- single exchange: (max, sum) per quarter ----
            if (tq == 0) {
                redA[ch * 64 + r0] = mx0;
                redA[ch * 64 + r1] = mx1;
                redB[ch * 64 + r0] = s0;
                redB[ch * 64 + r1] = s1;
            }
            __syncthreads();

            float mq0[4], mq1[4], sq0[4], sq1[4];
#pragma unroll
            for (int q = 0; q < 4; q++) {
                mq0[q] = redA[q * 64 + r0];
                mq1[q] = redA[q * 64 + r1];
                sq0[q] = redB[q * 64 + r0];
                sq1[q] = redB[q * 64 + r1];
            }
            const float mn0 = fmaxf(fmaxf(m0, fmaxf(mq0[0], mq0[1])),
                                    fmaxf(mq0[2], mq0[3]));
            const float mn1 = fmaxf(fmaxf(m1, fmaxf(mq1[0], mq1[1])),
                                    fmaxf(mq1[2], mq1[3]));
            const float al0 = __expf(m0 - mn0);
            const float al1 = __expf(m1 - mn1);
            float acc_l0 = 0.f, acc_l1 = 0.f, f0 = 0.f, f1 = 0.f;
#pragma unroll
            for (int q = 0; q < 4; q++) {
                float e0 = __expf(mq0[q] - mn0);
                float e1 = __expf(mq1[q] - mn1);
                acc_l0 += sq0[q] * e0;
                acc_l1 += sq1[q] * e1;
                if (q == ch) { f0 = e0; f1 = e1; }
            }
            l0 = l0 * al0 + acc_l0;
            l1 = l1 * al1 + acc_l1;
            m0 = mn0; m1 = mn1;

            // ---- rescale P to global max, split to bf16 hi/lo ----
            uint32_t ph[2], pl[2], ph2[2], pl2[2];
#pragma unroll
            for (int j = 0; j < 2; j++) {
                split2(make_float2(sacc[j][0] * f0, sacc[j][1] * f0), ph[j],  pl[j]);
                split2(make_float2(sacc[j][2] * f1, sacc[j][3] * f1), ph2[j], pl2[j]);
            }

            // ---- rescale O, then O += P @ V (warp's 16 kv rows of V) ----
#pragma unroll
            for (int j = 0; j < 8; j++) {
                oacc[j][0] *= al0; oacc[j][1] *= al0;
                oacc[j][2] *= al1; oacc[j][3] *= al1;
            }
            {
                uint32_t Aph[4] = {ph[0], ph2[0], ph[1], ph2[1]};
                uint32_t Apl[4] = {pl[0], pl2[0], pl[1], pl2[1]};
                const uint32_t vbase = stg + 18432;
                const uint32_t vrow = (16 * ch + lrow) * ASTR;
#pragma unroll
                for (int jj = 0; jj < 4; jj++) {
                    uint32_t vh[4], vl[4];
                    const uint32_t coff = (16 * jj + lcol) * 2;
                    ldmx4t(vh, vbase + vrow + coff);
                    ldmx4t(vl, vbase + 9216 + vrow + coff);
                    mma16816(oacc[2 * jj],     Aph, make_uint2(vh[0], vh[1]));
                    mma16816(oacc[2 * jj + 1], Aph, make_uint2(vh[2], vh[3]));
                    mma16816(oacc[2 * jj],     Aph, make_uint2(vl[0], vl[1]));
                    mma16816(oacc[2 * jj + 1], Aph, make_uint2(vl[2], vl[3]));
                    mma16816(oacc[2 * jj],     Apl, make_uint2(vh[0], vh[1]));
                    mma16816(oacc[2 * jj + 1], Apl, make_uint2(vh[2], vh[3]));
                }
            }
            // no end-of-iter sync: next iteration's CP_WAIT0 + sync covers reuse
        }
        __syncthreads();   // all warps done with last KV stage before OB reuse

        // ---- epilogue: 4-way O reduction across col-quarters, normalize ----
        float* ob = (float*)(smem + SM_OB);
        if (ch != 0) {
            float* dst = ob + (ch - 1) * 4352;   // 64 rows * 68 floats
#pragma unroll
            for (int j = 0; j < 8; j++) {
                *(float2*)(dst + r0 * 68 + 8 * j + 2 * tq) =
                    make_float2(oacc[j][0], oacc[j][1]);
                *(float2*)(dst + r1 * 68 + 8 * j + 2 * tq) =
                    make_float2(oacc[j][2], oacc[j][3]);
            }
        }
        __syncthreads();
        if (ch == 0) {
            const float inv0 = 1.0f / l0;
            const float inv1 = 1.0f / l1;
            float* out0 = Out + ((size_t)b * TT + q0 + r0) * HH;
            float* out1 = Out + ((size_t)b * TT + q0 + r1) * HH;
#pragma unroll
            for (int j = 0; j < 8; j++) {
                const int c = 8 * j + 2 * tq;
                float2 a0 = *(float2*)(ob + r0 * 68 + c);
                float2 b0 = *(float2*)(ob + 4352 + r0 * 68 + c);
                float2 c0 = *(float2*)(ob + 8704 + r0 * 68 + c);
                float2 a1 = *(float2*)(ob + r1 * 68 + c);
                float2 b1 = *(float2*)(ob + 4352 + r1 * 68 + c);
                float2 c1 = *(float2*)(ob + 8704 + r1 * 68 + c);
                *(float2*)(out0 + c) = make_float2(
                    (oacc[j][0] + a0.x + b0.x + c0.x) * inv0,
                    (oacc[j][1] + a0.y + b0.y + c0.y) * inv0);
                *(float2*)(out1 + c) = make_float2(
                    (oacc[j][2] + a1.x + b1.x + c1.x) * inv1,
                    (oacc[j][3] + a1.y + b1.y + c1.y) * inv1);
            }
        }
        __syncthreads();   // smem (Q region, OB) safe before next pi's issues
    }
}

// ---------------------------------------------------------------------------
extern "C" void kernel_launch(void* const* d_in, const int* in_sizes, int n_in,
                              void* d_out, int out_size)
{
    const float* x  = (const float*)d_in[0];
    const float* Wq = (const float*)d_in[1];
    const float* Wk = (const float*)d_in[2];
    const float* Wv = (const float*)d_in[3];
    float* out = (float*)d_out;

    cudaFuncSetAttribute(qkv_mma_kernel,
                         cudaFuncAttributeMaxDynamicSharedMemorySize, QS_TOTAL);
    cudaFuncSetAttribute(attn_kernel,
                         cudaFuncAttributeMaxDynamicSharedMemorySize, ATTN_SMEM);

    wprep_kernel<<<192, 256>>>(Wq, Wk, Wv);
    qkv_mma_kernel<<<MTOT / 128, 256, QS_TOTAL>>>(x);
    attn_kernel<<<dim3(16, BB), 512, ATTN_SMEM>>>(out);
}

// round 11
// speedup vs baseline: 1.2638x; 1.2638x over previous
#include <cuda_runtime.h>
#include <cuda_bf16.h>
#include <cuda_fp16.h>
#include <cstdint>

// Problem constants
#define BB   8
#define TT   2048
#define DD   1024
#define HH   64
#define MTOT (BB * TT)   // 16384

// fp16 Q,K (single, Q pre-scaled 1/8) and fp16 hi/lo V from the projection.
__device__ __half g_q16[(size_t)MTOT * HH];
__device__ __half g_k16[(size_t)MTOT * HH];
__device__ __half g_vH16[(size_t)MTOT * HH];
__device__ __half g_vL16[(size_t)MTOT * HH];
// Split-precision transposed weights (bf16, for the projection GEMM)
__device__ __nv_bfloat16 g_WtH[192 * 1024];
__device__ __nv_bfloat16 g_WtL[192 * 1024];

// ===========================================================================
// Helpers (plain sm_100-compatible: mma.sync + cp.async + ldmatrix)
// ===========================================================================
__device__ __forceinline__ uint32_t smem_u32(const void* p) {
    uint32_t a;
    asm("{ .reg .u64 t; cvta.to.shared.u64 t, %1; cvt.u32.u64 %0, t; }"
        : "=r"(a) : "l"(p));
    return a;
}
#define CP_ASYNC16(dst, src) \
    asm volatile("cp.async.cg.shared.global [%0], [%1], 16;" \
                 :: "r"(dst), "l"(src) : "memory")
#define CP_COMMIT() asm volatile("cp.async.commit_group;" ::: "memory")
#define CP_WAIT1()  asm volatile("cp.async.wait_group 1;" ::: "memory")
#define CP_WAIT0()  asm volatile("cp.async.wait_group 0;" ::: "memory")

// split one float2 into packed bf16x2 hi and residual-lo fragments
__device__ __forceinline__ void split2(float2 f, uint32_t& hi, uint32_t& lo) {
    uint32_t h;
    asm("cvt.rn.bf16x2.f32 %0, %1, %2;" : "=r"(h) : "f"(f.y), "f"(f.x));
    float hf0 = __uint_as_float(h << 16);
    float hf1 = __uint_as_float(h & 0xffff0000u);
    float l0 = f.x - hf0;
    float l1 = f.y - hf1;
    asm("cvt.rn.bf16x2.f32 %0, %1, %2;" : "=r"(lo) : "f"(l1), "f"(l0));
    hi = h;
}

// bf16 mma (projection kernel)
__device__ __forceinline__ void mma16816(float* c, const uint32_t* a, uint2 b) {
    asm volatile(
        "mma.sync.aligned.m16n8k16.row.col.f32.bf16.bf16.f32 "
        "{%0,%1,%2,%3}, {%4,%5,%6,%7}, {%8,%9}, {%0,%1,%2,%3};"
        : "+f"(c[0]), "+f"(c[1]), "+f"(c[2]), "+f"(c[3])
        : "r"(a[0]), "r"(a[1]), "r"(a[2]), "r"(a[3]), "r"(b.x), "r"(b.y));
}
// fp16 mma (attention kernel)
__device__ __forceinline__ void mma16816h(float* c, const uint32_t* a, uint2 b) {
    asm volatile(
        "mma.sync.aligned.m16n8k16.row.col.f32.f16.f16.f32 "
        "{%0,%1,%2,%3}, {%4,%5,%6,%7}, {%8,%9}, {%0,%1,%2,%3};"
        : "+f"(c[0]), "+f"(c[1]), "+f"(c[2]), "+f"(c[3])
        : "r"(a[0]), "r"(a[1]), "r"(a[2]), "r"(a[3]), "r"(b.x), "r"(b.y));
}

__device__ __forceinline__ void ldmx4t(uint32_t* r, uint32_t addr) {
    asm volatile("ldmatrix.sync.aligned.m8n8.x4.trans.shared.b16 "
                 "{%0,%1,%2,%3}, [%4];"
                 : "=r"(r[0]), "=r"(r[1]), "=r"(r[2]), "=r"(r[3]) : "r"(addr));
}

// ===========================================================================
// Kernel 0: W prep (unchanged, passing).
// ===========================================================================
__global__ __launch_bounds__(256) void wprep_kernel(
    const float* __restrict__ Wq,
    const float* __restrict__ Wk,
    const float* __restrict__ Wv)
{
    const int n = blockIdx.x;                 // 0..191
    const float* W = (n < 64) ? Wq : ((n < 128) ? Wk : Wv);
    const int nn = n & 63;
    for (int k = threadIdx.x; k < 1024; k += 256) {
        float w = W[(size_t)k * 64 + nn];
        __nv_bfloat16 h = __float2bfloat16(w);
        float r = w - __bfloat162float(h);
        int p   = (k & 15) >> 1;
        int pos = (k & ~15) + (p & 3) * 4 + (p >> 2) * 2 + (k & 1);
        g_WtH[(size_t)n * 1024 + pos] = h;
        g_WtL[(size_t)n * 1024 + pos] = __float2bfloat16(r);
    }
}

// ===========================================================================
// Kernel 1: QKV projection via mma.sync bf16 split precision (mainloop
// unchanged). Epilogue emits fp16 q,k (single; q scaled 1/8) + fp16 hi/lo v.
// ===========================================================================
#define XS_STRIDE 272
#define WS_STRIDE 144
#define XS_BYTES  (128 * XS_STRIDE)
#define WS_BYTES  (192 * WS_STRIDE)
#define QS_STAGE  (XS_BYTES + 2 * WS_BYTES)
#define QS_TOTAL  (2 * QS_STAGE)

__global__ __launch_bounds__(256, 1) void qkv_mma_kernel(const float* __restrict__ X)
{
    extern __shared__ char smem[];
    const uint32_t sb = smem_u32(smem);
    const int tid  = threadIdx.x;
    const int wid  = tid >> 5;
    const int lane = tid & 31;
    const int gid  = lane >> 2;
    const int tq   = lane & 3;
    const int wm   = (wid & 3) * 32;
    const int wn   = (wid >> 2) * 96;

    const char* Xg = (const char*)(X + (size_t)blockIdx.x * 128 * DD);
    const char* WHg = (const char*)g_WtH;
    const char* WLg = (const char*)g_WtL;

    auto issue = [&](int c, int s) {
        const uint32_t st = sb + s * QS_STAGE;
        const char* xs = Xg + c * 256;
#pragma unroll
        for (int i = 0; i < 8; i++) {
            int u = tid + 256 * i;
            int r = u >> 4, col = u & 15;
            CP_ASYNC16(st + r * XS_STRIDE + col * 16, xs + (size_t)r * 4096 + col * 16);
        }
        const uint32_t wh = st + XS_BYTES;
        const uint32_t wl = wh + WS_BYTES;
        const char* whs = WHg + c * 128;
        const char* wls = WLg + c * 128;
#pragma unroll
        for (int i = 0; i < 6; i++) {
            int u = tid + 256 * i;
            int n = u >> 3, col = u & 7;
            CP_ASYNC16(wh + n * WS_STRIDE + col * 16, whs + (size_t)n * 2048 + col * 16);
            CP_ASYNC16(wl + n * WS_STRIDE + col * 16, wls + (size_t)n * 2048 + col * 16);
        }
        CP_COMMIT();
    };

    float acc[2][12][4];
#pragma unroll
    for (int m = 0; m < 2; m++)
#pragma unroll
        for (int j = 0; j < 12; j++) {
            acc[m][j][0] = 0.f; acc[m][j][1] = 0.f;
            acc[m][j][2] = 0.f; acc[m][j][3] = 0.f;
        }

    issue(0, 0);

    for (int c = 0; c < 16; c++) {
        const int s = c & 1;
        if (c < 15) { issue(c + 1, s ^ 1); CP_WAIT1(); }
        else        { CP_WAIT0(); }
        __syncthreads();

        const char* Xs = smem + s * QS_STAGE;
        const char* Wh = Xs + XS_BYTES;
        const char* Wl = Wh + WS_BYTES;

#pragma unroll
        for (int ks = 0; ks < 4; ks++) {
            uint32_t Ah[2][4], Al[2][4];
#pragma unroll
            for (int m = 0; m < 2; m++) {
                const int r0 = wm + m * 16 + gid;
                const char* base = Xs + (size_t)r0 * XS_STRIDE + ks * 64 + tq * 8;
                float2 f0 = *(const float2*)(base);
                float2 f1 = *(const float2*)(base + 8 * XS_STRIDE);
                float2 f2 = *(const float2*)(base + 32);
                float2 f3 = *(const float2*)(base + 8 * XS_STRIDE + 32);
                split2(f0, Ah[m][0], Al[m][0]);
                split2(f1, Ah[m][1], Al[m][1]);
                split2(f2, Ah[m][2], Al[m][2]);
                split2(f3, Ah[m][3], Al[m][3]);
            }
#pragma unroll
            for (int j = 0; j < 12; j++) {
                const size_t boff = (size_t)(wn + j * 8 + gid) * WS_STRIDE + ks * 32 + tq * 8;
                uint2 bh = *(const uint2*)(Wh + boff);
                uint2 bl = *(const uint2*)(Wl + boff);
#pragma unroll
                for (int m = 0; m < 2; m++) {
                    mma16816(acc[m][j], Ah[m], bh);
                    mma16816(acc[m][j], Ah[m], bl);
                    mma16816(acc[m][j], Al[m], bh);
                }
            }
        }
        __syncthreads();
    }

    // ---- epilogue: fp16 outputs (q scaled 1/8; v split into fp16 hi/lo) ----
#pragma unroll
    for (int m = 0; m < 2; m++) {
        const size_t row = (size_t)blockIdx.x * 128 + wm + m * 16 + gid;
#pragma unroll
        for (int j = 0; j < 12; j++) {
            const int nc = wn + j * 8 + tq * 2;
            const int g  = nc >> 6;
            const int cc = nc & 63;
            const float a0 = acc[m][j][0], a1 = acc[m][j][1];
            const float a2 = acc[m][j][2], a3 = acc[m][j][3];
            if (g == 0) {
                *(__half2*)(g_q16 + row * HH + cc) =
                    __floats2half2_rn(a0 * 0.125f, a1 * 0.125f);
                *(__half2*)(g_q16 + (row + 8) * HH + cc) =
                    __floats2half2_rn(a2 * 0.125f, a3 * 0.125f);
            } else if (g == 1) {
                *(__half2*)(g_k16 + row * HH + cc) = __floats2half2_rn(a0, a1);
                *(__half2*)(g_k16 + (row + 8) * HH + cc) = __floats2half2_rn(a2, a3);
            } else {
                __half2 h0 = __floats2half2_rn(a0, a1);
                __half2 h1 = __floats2half2_rn(a2, a3);
                float2 f0 = __half22float2(h0);
                float2 f1 = __half22float2(h1);
                *(__half2*)(g_vH16 + row * HH + cc)       = h0;
                *(__half2*)(g_vH16 + (row + 8) * HH + cc) = h1;
                *(__half2*)(g_vL16 + row * HH + cc) =
                    __floats2half2_rn(a0 - f0.x, a1 - f0.y);
                *(__half2*)(g_vL16 + (row + 8) * HH + cc) =
                    __floats2half2_rn(a2 - f1.x, a3 - f1.y);
            }
        }
    }
}

// ===========================================================================
// Kernel 2: flash attention (causal) — fp16 mma.sync, round-7 structure.
// S = q16 @ k16^T  (single product).  PV = P16 @ (Vh + Vl)  (2 products).
// q-tile 64, kv-tile 64, pairing {g, 31-g} -> 33 iters/block, 128 blocks.
// ===========================================================================
#define ASTR      144        // smem tile row stride (64*2 B + 16 pad)
#define SM_Q      0
#define SM_KV     9216
#define KV_STAGE  27648      // K, VH, VL at +0, +9216, +18432
#define SM_RA     64512      // float[2][64]
#define SM_RB     65024      // float[2][64]
#define SM_OB     9216       // epilogue O buffer (overlaps KV stages)
#define ATTN_SMEM 65536

__global__ __launch_bounds__(256, 1) void attn_kernel(float* __restrict__ Out)
{
    extern __shared__ char smem[];
    const uint32_t sb = smem_u32(smem);

    const int b = blockIdx.y;
    const int g = blockIdx.x;
    const int tid  = threadIdx.x;
    const int wid  = tid >> 5;
    const int lane = tid & 31;
    const int ch   = wid >> 2;     // kv col half (0: 0-31, 1: 32-63)
    const int rg   = wid & 3;      // q row group (16 rows)
    const int gid  = lane >> 2;
    const int tq   = lane & 3;

    const size_t boff = (size_t)b * TT * HH * 2;   // byte offset for this batch
    const char* qg  = (const char*)g_q16 + boff;
    const char* kg  = (const char*)g_k16 + boff;
    const char* vHg = (const char*)g_vH16 + boff;
    const char* vLg = (const char*)g_vL16 + boff;

    float* redA = (float*)(smem + SM_RA);
    float* redB = (float*)(smem + SM_RB);

    const int r0 = 16 * rg + gid;       // this thread's q rows (local)
    const int r1 = r0 + 8;

    // ldmatrix lane address components for transposed V loads
    const int lrow = (lane & 7) + ((lane >> 3) & 1) * 8;
    const int lcol = (lane >> 4) * 8;

    // async loaders -------------------------------------------------------
    auto issue_q = [&](int q0) {
#pragma unroll
        for (int i = 0; i < 2; i++) {
            int u = tid + 256 * i;             // 0..511
            int r = u >> 3;
            int cc = u & 7;
            CP_ASYNC16(sb + SM_Q + r * ASTR + cc * 16,
                       qg + (size_t)(q0 + r) * 128 + cc * 16);
        }
        CP_COMMIT();
    };
    auto issue_kv = [&](int k0, int s) {
        const uint32_t base = sb + SM_KV + s * KV_STAGE;
#pragma unroll
        for (int i = 0; i < 6; i++) {
            int u = tid + 256 * i;             // 0..1535
            int t = u / 512;                   // 0: K, 1: VH, 2: VL
            int r = (u >> 3) & 63;
            int cc = u & 7;
            const char* src = (t == 0 ? kg : t == 1 ? vHg : vLg)
                              + (size_t)(k0 + r) * 128 + cc * 16;
            CP_ASYNC16(base + t * 9216 + r * ASTR + cc * 16, src);
        }
        CP_COMMIT();
    };

    for (int pi = 0; pi < 2; pi++) {
        const int qt = pi ? (31 - g) : g;
        const int q0 = qt * 64;

        issue_q(q0);
        issue_kv(0, 0);

        float m0 = -1e30f, m1 = -1e30f, l0 = 0.f, l1 = 0.f;
        float oacc[8][4];
#pragma unroll
        for (int j = 0; j < 8; j++) {
            oacc[j][0] = 0.f; oacc[j][1] = 0.f; oacc[j][2] = 0.f; oacc[j][3] = 0.f;
        }

        for (int kt = 0; kt <= qt; kt++) {
            if (kt < qt) { issue_kv((kt + 1) * 64, (kt + 1) & 1); CP_WAIT1(); }
            else         { CP_WAIT0(); }
            __syncthreads();

            const char* stg = smem + SM_KV + (kt & 1) * KV_STAGE;

            // ---- S = Q @ K^T (single fp16 product) ----
            float sacc[4][4];
#pragma unroll
            for (int j = 0; j < 4; j++) {
                sacc[j][0] = 0.f; sacc[j][1] = 0.f; sacc[j][2] = 0.f; sacc[j][3] = 0.f;
            }
            {
                const char* qh = smem + SM_Q + r0 * ASTR + tq * 4;
                const char* kh = stg + (32 * ch + gid) * ASTR + tq * 4;
#pragma unroll
                for (int kb = 0; kb < 4; kb++) {
                    uint32_t A[4];
                    A[0] = *(const uint32_t*)(qh + kb * 32);
                    A[1] = *(const uint32_t*)(qh + 8 * ASTR + kb * 32);
                    A[2] = *(const uint32_t*)(qh + kb * 32 + 16);
                    A[3] = *(const uint32_t*)(qh + 8 * ASTR + kb * 32 + 16);
#pragma unroll
                    for (int j = 0; j < 4; j++) {
                        uint2 bh;
                        bh.x = *(const uint32_t*)(kh + j * 8 * ASTR + kb * 32);
                        bh.y = *(const uint32_t*)(kh + j * 8 * ASTR + kb * 32 + 16);
                        mma16816h(sacc[j], A, bh);
                    }
                }
            }

            // ---- causal mask + partial row max ----
            const bool diag = (kt == qt);
            float mx0 = -1e30f, mx1 = -1e30f;
#pragma unroll
            for (int j = 0; j < 4; j++) {
                const int c0 = 32 * ch + 8 * j + 2 * tq;
                if (diag) {
                    if (c0     > r0) sacc[j][0] = -1e30f;
                    if (c0 + 1 > r0) sacc[j][1] = -1e30f;
                    if (c0     > r1) sacc[j][2] = -1e30f;
                    if (c0 + 1 > r1) sacc[j][3] = -1e30f;
                }
                mx0 = fmaxf(mx0, fmaxf(sacc[j][0], sacc[j][1]));
                mx1 = fmaxf(mx1, fmaxf(sacc[j][2], sacc[j][3]));
            }
            mx0 = fmaxf(mx0, __shfl_xor_sync(0xffffffffu, mx0, 1));
            mx0 = fmaxf(mx0, __shfl_xor_sync(0xffffffffu, mx0, 2));
            mx1 = fmaxf(mx1, __shfl_xor_sync(0xffffffffu, mx1, 1));
            mx1 = fmaxf(mx1, __shfl_xor_sync(0xffffffffu, mx1, 2));
            if (tq == 0) {
                redA[ch * 64 + r0] = mx0;
                redA[ch * 64 + r1] = mx1;
            }
            __syncthreads();

            // ---- full row max, exp, partial sums ----
            const float om0 = m0, om1 = m1;
            m0 = fmaxf(m0, fmaxf(redA[r0], redA[64 + r0]));
            m1 = fmaxf(m1, fmaxf(redA[r1], redA[64 + r1]));
            const float al0 = __expf(om0 - m0);
            const float al1 = __expf(om1 - m1);
            float s0 = 0.f, s1 = 0.f;
#pragma unroll
            for (int j = 0; j < 4; j++) {
                sacc[j][0] = __expf(sacc[j][0] - m0);
                sacc[j][1] = __expf(sacc[j][1] - m0);
                sacc[j][2] = __expf(sacc[j][2] - m1);
                sacc[j][3] = __expf(sacc[j][3] - m1);
                s0 += sacc[j][0] + sacc[j][1];
                s1 += sacc[j][2] + sacc[j][3];
            }
            s0 += __shfl_xor_sync(0xffffffffu, s0, 1);
            s0 += __shfl_xor_sync(0xffffffffu, s0, 2);
            s1 += __shfl_xor_sync(0xffffffffu, s1, 1);
            s1 += __shfl_xor_sync(0xffffffffu, s1, 2);
            if (tq == 0) {
                redB[ch * 64 + r0] = s0;
                redB[ch * 64 + r1] = s1;
            }

            // ---- pack P to single fp16 (registers only) ----
            uint32_t ph[4], ph2[4];
#pragma unroll
            for (int j = 0; j < 4; j++) {
                __half2 t0 = __floats2half2_rn(sacc[j][0], sacc[j][1]);
                __half2 t1 = __floats2half2_rn(sacc[j][2], sacc[j][3]);
                ph[j]  = *(uint32_t*)&t0;
                ph2[j] = *(uint32_t*)&t1;
            }

            // ---- rescale O, then O += P @ (Vh + Vl) ----
#pragma unroll
            for (int j = 0; j < 8; j++) {
                oacc[j][0] *= al0; oacc[j][1] *= al0;
                oacc[j][2] *= al1; oacc[j][3] *= al1;
            }
            const uint32_t vbase = sb + SM_KV + (kt & 1) * KV_STAGE + 9216;
#pragma unroll
            for (int kb = 0; kb < 2; kb++) {
                uint32_t Aph[4] = {ph[2 * kb], ph2[2 * kb], ph[2 * kb + 1], ph2[2 * kb + 1]};
                const uint32_t vrow = (32 * ch + 16 * kb + lrow) * ASTR;
#pragma unroll
                for (int jj = 0; jj < 4; jj++) {
                    uint32_t vh[4], vl[4];
                    const uint32_t coff = (16 * jj + lcol) * 2;
                    ldmx4t(vh, vbase + vrow + coff);
                    ldmx4t(vl, vbase + 9216 + vrow + coff);
                    mma16816h(oacc[2 * jj],     Aph, make_uint2(vh[0], vh[1]));
                    mma16816h(oacc[2 * jj + 1], Aph, make_uint2(vh[2], vh[3]));
                    mma16816h(oacc[2 * jj],     Aph, make_uint2(vl[0], vl[1]));
                    mma16816h(oacc[2 * jj + 1], Aph, make_uint2(vl[2], vl[3]));
                }
            }
            __syncthreads();   // protect KV stage + redB for next iteration

            l0 = l0 * al0 + redB[r0] + redB[64 + r0];
            l1 = l1 * al1 + redB[r1] + redB[64 + r1];
        }

        // ---- epilogue: reduce O halves across warp pairs, normalize, store ----
        float* ob = (float*)(smem + SM_OB);
        if (ch == 1) {
#pragma unroll
            for (int j = 0; j < 8; j++) {
                *(float2*)(ob + r0 * 68 + 8 * j + 2 * tq) =
                    make_float2(oacc[j][0], oacc[j][1]);
                *(float2*)(ob + r1 * 68 + 8 * j + 2 * tq) =
                    make_float2(oacc[j][2], oacc[j][3]);
            }
        }
        __syncthreads();
        if (ch == 0) {
            const float inv0 = 1.0f / l0;
            const float inv1 = 1.0f / l1;
            float* out0 = Out + ((size_t)b * TT + q0 + r0) * HH;
            float* out1 = Out + ((size_t)b * TT + q0 + r1) * HH;
#pragma unroll
            for (int j = 0; j < 8; j++) {
                float2 p0 = *(float2*)(ob + r0 * 68 + 8 * j + 2 * tq);
                float2 p1 = *(float2*)(ob + r1 * 68 + 8 * j + 2 * tq);
                *(float2*)(out0 + 8 * j + 2 * tq) =
                    make_float2((oacc[j][0] + p0.x) * inv0, (oacc[j][1] + p0.y) * inv0);
                *(float2*)(out1 + 8 * j + 2 * tq) =
                    make_float2((oacc[j][2] + p1.x) * inv1, (oacc[j][3] + p1.y) * inv1);
            }
        }
        __syncthreads();   // smem (Q region, OB) safe before next pi's issues
    }
}

// ---------------------------------------------------------------------------
extern "C" void kernel_launch(void* const* d_in, const int* in_sizes, int n_in,
                              void* d_out, int out_size)
{
    const float* x  = (const float*)d_in[0];
    const float* Wq = (const float*)d_in[1];
    const float* Wk = (const float*)d_in[2];
    const float* Wv = (const float*)d_in[3];
    float* out = (float*)d_out;

    cudaFuncSetAttribute(qkv_mma_kernel,
                         cudaFuncAttributeMaxDynamicSharedMemorySize, QS_TOTAL);
    cudaFuncSetAttribute(attn_kernel,
                         cudaFuncAttributeMaxDynamicSharedMemorySize, ATTN_SMEM);

    wprep_kernel<<<192, 256>>>(Wq, Wk, Wv);
    qkv_mma_kernel<<<MTOT / 128, 256, QS_TOTAL>>>(x);
    attn_kernel<<<dim3(16, BB), 256, ATTN_SMEM>>>(out);
}

// round 12
// speedup vs baseline: 1.3610x; 1.0769x over previous
#include <cuda_runtime.h>
#include <cuda_bf16.h>
#include <cuda_fp16.h>
#include <cstdint>

// Problem constants
#define BB   8
#define TT   2048
#define DD   1024
#define HH   64
#define MTOT (BB * TT)   // 16384

// fp16 Q,K (single, Q pre-scaled 1/8) and fp16 hi/lo V from the projection.
__device__ __half g_q16[(size_t)MTOT * HH];
__device__ __half g_k16[(size_t)MTOT * HH];
__device__ __half g_vH16[(size_t)MTOT * HH];
__device__ __half g_vL16[(size_t)MTOT * HH];
// fp16 hi/lo transposed weights (for the 2-product projection GEMM)
__device__ __half g_WtH[192 * 1024];
__device__ __half g_WtL[192 * 1024];

// ===========================================================================
// Helpers (plain sm_100-compatible: mma.sync + cp.async + ldmatrix)
// ===========================================================================
__device__ __forceinline__ uint32_t smem_u32(const void* p) {
    uint32_t a;
    asm("{ .reg .u64 t; cvta.to.shared.u64 t, %1; cvt.u32.u64 %0, t; }"
        : "=r"(a) : "l"(p));
    return a;
}
#define CP_ASYNC16(dst, src) \
    asm volatile("cp.async.cg.shared.global [%0], [%1], 16;" \
                 :: "r"(dst), "l"(src) : "memory")
#define CP_COMMIT() asm volatile("cp.async.commit_group;" ::: "memory")
#define CP_WAIT1()  asm volatile("cp.async.wait_group 1;" ::: "memory")
#define CP_WAIT0()  asm volatile("cp.async.wait_group 0;" ::: "memory")

// fp16 mma, fp32 accumulate
__device__ __forceinline__ void mma16816h(float* c, const uint32_t* a, uint2 b) {
    asm volatile(
        "mma.sync.aligned.m16n8k16.row.col.f32.f16.f16.f32 "
        "{%0,%1,%2,%3}, {%4,%5,%6,%7}, {%8,%9}, {%0,%1,%2,%3};"
        : "+f"(c[0]), "+f"(c[1]), "+f"(c[2]), "+f"(c[3])
        : "r"(a[0]), "r"(a[1]), "r"(a[2]), "r"(a[3]), "r"(b.x), "r"(b.y));
}

__device__ __forceinline__ void ldmx4t(uint32_t* r, uint32_t addr) {
    asm volatile("ldmatrix.sync.aligned.m8n8.x4.trans.shared.b16 "
                 "{%0,%1,%2,%3}, [%4];"
                 : "=r"(r[0]), "=r"(r[1]), "=r"(r[2]), "=r"(r[3]) : "r"(addr));
}

// ===========================================================================
// Kernel 0: W prep — smem-tiled transpose, fp16 hi/lo outputs.
// Input W[g]: [1024, 64] fp32. Output rows n (=output col), K-major, with the
// in-k16 pair permutation matching the B-fragment layout.
// grid (16, 3): block handles 64 k-rows of one W.
// ===========================================================================
__global__ __launch_bounds__(256) void wprep_kernel(
    const float* __restrict__ Wq,
    const float* __restrict__ Wk,
    const float* __restrict__ Wv)
{
    __shared__ float tile[64][65];
    const int g  = blockIdx.y;
    const float* W = (g == 0) ? Wq : ((g == 1) ? Wk : Wv);
    const int k0 = blockIdx.x * 64;

#pragma unroll
    for (int i = 0; i < 16; i++) {
        int idx = threadIdx.x + 256 * i;
        int r = idx >> 6, c = idx & 63;
        tile[r][c] = W[(size_t)(k0 + r) * 64 + c];   // coalesced
    }
    __syncthreads();
#pragma unroll
    for (int i = 0; i < 16; i++) {
        int idx = threadIdx.x + 256 * i;
        int n = idx >> 6, r = idx & 63;
        float w = tile[r][n];                         // stride-65: conflict-free
        __half h = __float2half_rn(w);
        float res = w - __half2float(h);
        int k = k0 + r;
        int p = (k & 15) >> 1;
        int pos = (k & ~15) + (p & 3) * 4 + (p >> 2) * 2 + (k & 1);
        g_WtH[(size_t)(g * 64 + n) * 1024 + pos] = h;
        g_WtL[(size_t)(g * 64 + n) * 1024 + pos] = __float2half_rn(res);
    }
}

// ===========================================================================
// Kernel 1: QKV projection — fp16 2-product split (x single fp16, W hi/lo).
// C[g][16384,64] = X @ W[g]. Per CTA: 128 rows x 192 cols. K chunks of 64,
// cp.async double-buffered. 8 warps = 4(m,32 rows) x 2(n,96 cols).
// Epilogue emits fp16 q,k (single; q scaled 1/8) + fp16 hi/lo v.
// ===========================================================================
#define XS_STRIDE 272
#define WS_STRIDE 144
#define XS_BYTES  (128 * XS_STRIDE)
#define WS_BYTES  (192 * WS_STRIDE)
#define QS_STAGE  (XS_BYTES + 2 * WS_BYTES)
#define QS_TOTAL  (2 * QS_STAGE)

__global__ __launch_bounds__(256, 1) void qkv_mma_kernel(const float* __restrict__ X)
{
    extern __shared__ char smem[];
    const uint32_t sb = smem_u32(smem);
    const int tid  = threadIdx.x;
    const int wid  = tid >> 5;
    const int lane = tid & 31;
    const int gid  = lane >> 2;
    const int tq   = lane & 3;
    const int wm   = (wid & 3) * 32;
    const int wn   = (wid >> 2) * 96;

    const char* Xg = (const char*)(X + (size_t)blockIdx.x * 128 * DD);
    const char* WHg = (const char*)g_WtH;
    const char* WLg = (const char*)g_WtL;

    auto issue = [&](int c, int s) {
        const uint32_t st = sb + s * QS_STAGE;
        const char* xs = Xg + c * 256;
#pragma unroll
        for (int i = 0; i < 8; i++) {
            int u = tid + 256 * i;
            int r = u >> 4, col = u & 15;
            CP_ASYNC16(st + r * XS_STRIDE + col * 16, xs + (size_t)r * 4096 + col * 16);
        }
        const uint32_t wh = st + XS_BYTES;
        const uint32_t wl = wh + WS_BYTES;
        const char* whs = WHg + c * 128;
        const char* wls = WLg + c * 128;
#pragma unroll
        for (int i = 0; i < 6; i++) {
            int u = tid + 256 * i;
            int n = u >> 3, col = u & 7;
            CP_ASYNC16(wh + n * WS_STRIDE + col * 16, whs + (size_t)n * 2048 + col * 16);
            CP_ASYNC16(wl + n * WS_STRIDE + col * 16, wls + (size_t)n * 2048 + col * 16);
        }
        CP_COMMIT();
    };

    float acc[2][12][4];
#pragma unroll
    for (int m = 0; m < 2; m++)
#pragma unroll
        for (int j = 0; j < 12; j++) {
            acc[m][j][0] = 0.f; acc[m][j][1] = 0.f;
            acc[m][j][2] = 0.f; acc[m][j][3] = 0.f;
        }

    issue(0, 0);

    for (int c = 0; c < 16; c++) {
        const int s = c & 1;
        if (c < 15) { issue(c + 1, s ^ 1); CP_WAIT1(); }
        else        { CP_WAIT0(); }
        __syncthreads();

        const char* Xs = smem + s * QS_STAGE;
        const char* Wh = Xs + XS_BYTES;
        const char* Wl = Wh + WS_BYTES;

#pragma unroll
        for (int ks = 0; ks < 4; ks++) {
            // ---- A fragments: load fp32, convert to single fp16 ----
            uint32_t A[2][4];
#pragma unroll
            for (int m = 0; m < 2; m++) {
                const int r0 = wm + m * 16 + gid;
                const char* base = Xs + (size_t)r0 * XS_STRIDE + ks * 64 + tq * 8;
                float2 f0 = *(const float2*)(base);
                float2 f1 = *(const float2*)(base + 8 * XS_STRIDE);
                float2 f2 = *(const float2*)(base + 32);
                float2 f3 = *(const float2*)(base + 8 * XS_STRIDE + 32);
                __half2 h0 = __floats2half2_rn(f0.x, f0.y);
                __half2 h1 = __floats2half2_rn(f1.x, f1.y);
                __half2 h2 = __floats2half2_rn(f2.x, f2.y);
                __half2 h3 = __floats2half2_rn(f3.x, f3.y);
                A[m][0] = *(uint32_t*)&h0;
                A[m][1] = *(uint32_t*)&h1;
                A[m][2] = *(uint32_t*)&h2;
                A[m][3] = *(uint32_t*)&h3;
            }
            // ---- B fragments + 2-product MMAs ----
#pragma unroll
            for (int j = 0; j < 12; j++) {
                const size_t boff = (size_t)(wn + j * 8 + gid) * WS_STRIDE + ks * 32 + tq * 8;
                uint2 bh = *(const uint2*)(Wh + boff);
                uint2 bl = *(const uint2*)(Wl + boff);
#pragma unroll
                for (int m = 0; m < 2; m++) {
                    mma16816h(acc[m][j], A[m], bh);
                    mma16816h(acc[m][j], A[m], bl);
                }
            }
        }
        __syncthreads();
    }

    // ---- epilogue: fp16 outputs (q scaled 1/8; v split into fp16 hi/lo) ----
#pragma unroll
    for (int m = 0; m < 2; m++) {
        const size_t row = (size_t)blockIdx.x * 128 + wm + m * 16 + gid;
#pragma unroll
        for (int j = 0; j < 12; j++) {
            const int nc = wn + j * 8 + tq * 2;
            const int g  = nc >> 6;
            const int cc = nc & 63;
            const float a0 = acc[m][j][0], a1 = acc[m][j][1];
            const float a2 = acc[m][j][2], a3 = acc[m][j][3];
            if (g == 0) {
                *(__half2*)(g_q16 + row * HH + cc) =
                    __floats2half2_rn(a0 * 0.125f, a1 * 0.125f);
                *(__half2*)(g_q16 + (row + 8) * HH + cc) =
                    __floats2half2_rn(a2 * 0.125f, a3 * 0.125f);
            } else if (g == 1) {
                *(__half2*)(g_k16 + row * HH + cc) = __floats2half2_rn(a0, a1);
                *(__half2*)(g_k16 + (row + 8) * HH + cc) = __floats2half2_rn(a2, a3);
            } else {
                __half2 h0 = __floats2half2_rn(a0, a1);
                __half2 h1 = __floats2half2_rn(a2, a3);
                float2 f0 = __half22float2(h0);
                float2 f1 = __half22float2(h1);
                *(__half2*)(g_vH16 + row * HH + cc)       = h0;
                *(__half2*)(g_vH16 + (row + 8) * HH + cc) = h1;
                *(__half2*)(g_vL16 + row * HH + cc) =
                    __floats2half2_rn(a0 - f0.x, a1 - f0.y);
                *(__half2*)(g_vL16 + (row + 8) * HH + cc) =
                    __floats2half2_rn(a2 - f1.x, a3 - f1.y);
            }
        }
    }
}

// ===========================================================================
// Kernel 2: flash attention (causal) — fp16 mma.sync (unchanged from r11).
// S = q16 @ k16^T (single product).  PV = P16 @ (Vh + Vl) (2 products).
// q-tile 64, kv-tile 64, pairing {g, 31-g} -> 33 iters/block, 128 blocks.
// ===========================================================================
#define ASTR      144        // smem tile row stride (64*2 B + 16 pad)
#define SM_Q      0
#define SM_KV     9216
#define KV_STAGE  27648      // K, VH, VL at +0, +9216, +18432
#define SM_RA     64512      // float[2][64]
#define SM_RB     65024      // float[2][64]
#define SM_OB     9216       // epilogue O buffer (overlaps KV stages)
#define ATTN_SMEM 65536

__global__ __launch_bounds__(256, 1) void attn_kernel(float* __restrict__ Out)
{
    extern __shared__ char smem[];
    const uint32_t sb = smem_u32(smem);

    const int b = blockIdx.y;
    const int g = blockIdx.x;
    const int tid  = threadIdx.x;
    const int wid  = tid >> 5;
    const int lane = tid & 31;
    const int ch   = wid >> 2;     // kv col half (0: 0-31, 1: 32-63)
    const int rg   = wid & 3;      // q row group (16 rows)
    const int gid  = lane >> 2;
    const int tq   = lane & 3;

    const size_t boff = (size_t)b * TT * HH * 2;   // byte offset for this batch
    const char* qg  = (const char*)g_q16 + boff;
    const char* kg  = (const char*)g_k16 + boff;
    const char* vHg = (const char*)g_vH16 + boff;
    const char* vLg = (const char*)g_vL16 + boff;

    float* redA = (float*)(smem + SM_RA);
    float* redB = (float*)(smem + SM_RB);

    const int r0 = 16 * rg + gid;       // this thread's q rows (local)
    const int r1 = r0 + 8;

    // ldmatrix lane address components for transposed V loads
    const int lrow = (lane & 7) + ((lane >> 3) & 1) * 8;
    const int lcol = (lane >> 4) * 8;

    // async loaders -------------------------------------------------------
    auto issue_q = [&](int q0) {
#pragma unroll
        for (int i = 0; i < 2; i++) {
            int u = tid + 256 * i;             // 0..511
            int r = u >> 3;
            int cc = u & 7;
            CP_ASYNC16(sb + SM_Q + r * ASTR + cc * 16,
                       qg + (size_t)(q0 + r) * 128 + cc * 16);
        }
        CP_COMMIT();
    };
    auto issue_kv = [&](int k0, int s) {
        const uint32_t base = sb + SM_KV + s * KV_STAGE;
#pragma unroll
        for (int i = 0; i < 6; i++) {
            int u = tid + 256 * i;             // 0..1535
            int t = u / 512;                   // 0: K, 1: VH, 2: VL
            int r = (u >> 3) & 63;
            int cc = u & 7;
            const char* src = (t == 0 ? kg : t == 1 ? vHg : vLg)
                              + (size_t)(k0 + r) * 128 + cc * 16;
            CP_ASYNC16(base + t * 9216 + r * ASTR + cc * 16, src);
        }
        CP_COMMIT();
    };

    for (int pi = 0; pi < 2; pi++) {
        const int qt = pi ? (31 - g) : g;
        const int q0 = qt * 64;

        issue_q(q0);
        issue_kv(0, 0);

        float m0 = -1e30f, m1 = -1e30f, l0 = 0.f, l1 = 0.f;
        float oacc[8][4];
#pragma unroll
        for (int j = 0; j < 8; j++) {
            oacc[j][0] = 0.f; oacc[j][1] = 0.f; oacc[j][2] = 0.f; oacc[j][3] = 0.f;
        }

        for (int kt = 0; kt <= qt; kt++) {
            if (kt < qt) { issue_kv((kt + 1) * 64, (kt + 1) & 1); CP_WAIT1(); }
            else         { CP_WAIT0(); }
            __syncthreads();

            const char* stg = smem + SM_KV + (kt & 1) * KV_STAGE;

            // ---- S = Q @ K^T (single fp16 product) ----
            float sacc[4][4];
#pragma unroll
            for (int j = 0; j < 4; j++) {
                sacc[j][0] = 0.f; sacc[j][1] = 0.f; sacc[j][2] = 0.f; sacc[j][3] = 0.f;
            }
            {
                const char* qh = smem + SM_Q + r0 * ASTR + tq * 4;
                const char* kh = stg + (32 * ch + gid) * ASTR + tq * 4;
#pragma unroll
                for (int kb = 0; kb < 4; kb++) {
                    uint32_t A[4];
                    A[0] = *(const uint32_t*)(qh + kb * 32);
                    A[1] = *(const uint32_t*)(qh + 8 * ASTR + kb * 32);
                    A[2] = *(const uint32_t*)(qh + kb * 32 + 16);
                    A[3] = *(const uint32_t*)(qh + 8 * ASTR + kb * 32 + 16);
#pragma unroll
                    for (int j = 0; j < 4; j++) {
                        uint2 bh;
                        bh.x = *(const uint32_t*)(kh + j * 8 * ASTR + kb * 32);
                        bh.y = *(const uint32_t*)(kh + j * 8 * ASTR + kb * 32 + 16);
                        mma16816h(sacc[j], A, bh);
                    }
                }
            }

            // ---- causal mask + partial row max ----
            const bool diag = (kt == qt);
            float mx0 = -1e30f, mx1 = -1e30f;
#pragma unroll
            for (int j = 0; j < 4; j++) {
                const int c0 = 32 * ch + 8 * j + 2 * tq;
                if (diag) {
                    if (c0     > r0) sacc[j][0] = -1e30f;
                    if (c0 + 1 > r0) sacc[j][1] = -1e30f;
                    if (c0     > r1) sacc[j][2] = -1e30f;
                    if (c0 + 1 > r1) sacc[j][3] = -1e30f;
                }
                mx0 = fmaxf(mx0, fmaxf(sacc[j][0], sacc[j][1]));
                mx1 = fmaxf(mx1, fmaxf(sacc[j][2], sacc[j][3]));
            }
            mx0 = fmaxf(mx0, __shfl_xor_sync(0xffffffffu, mx0, 1));
            mx0 = fmaxf(mx0, __shfl_xor_sync(0xffffffffu, mx0, 2));
            mx1 = fmaxf(mx1, __shfl_xor_sync(0xffffffffu, mx1, 1));
            mx1 = fmaxf(mx1, __shfl_xor_sync(0xffffffffu, mx1, 2));
            if (tq == 0) {
                redA[ch * 64 + r0] = mx0;
                redA[ch * 64 + r1] = mx1;
            }
            __syncthreads();

            // ---- full row max, exp, partial sums ----
            const float om0 = m0, om1 = m1;
            m0 = fmaxf(m0, fmaxf(redA[r0], redA[64 + r0]));
            m1 = fmaxf(m1, fmaxf(redA[r1], redA[64 + r1]));
            const float al0 = __expf(om0 - m0);
            const float al1 = __expf(om1 - m1);
            float s0 = 0.f, s1 = 0.f;
#pragma unroll
            for (int j = 0; j < 4; j++) {
                sacc[j][0] = __expf(sacc[j][0] - m0);
                sacc[j][1] = __expf(sacc[j][1] - m0);
                sacc[j][2] = __expf(sacc[j][2] - m1);
                sacc[j][3] = __expf(sacc[j][3] - m1);
                s0 += sacc[j][0] + sacc[j][1];
                s1 += sacc[j][2] + sacc[j][3];
            }
            s0 += __shfl_xor_sync(0xffffffffu, s0, 1);
            s0 += __shfl_xor_sync(0xffffffffu, s0, 2);
            s1 += __shfl_xor_sync(0xffffffffu, s1, 1);
            s1 += __shfl_xor_sync(0xffffffffu, s1, 2);
            if (tq == 0) {
                redB[ch * 64 + r0] = s0;
                redB[ch * 64 + r1] = s1;
            }

            // ---- pack P to single fp16 (registers only) ----
            uint32_t ph[4], ph2[4];
#pragma unroll
            for (int j = 0; j < 4; j++) {
                __half2 t0 = __floats2half2_rn(sacc[j][0], sacc[j][1]);
                __half2 t1 = __floats2half2_rn(sacc[j][2], sacc[j][3]);
                ph[j]  = *(uint32_t*)&t0;
                ph2[j] = *(uint32_t*)&t1;
            }

            // ---- rescale O, then O += P @ (Vh + Vl) ----
#pragma unroll
            for (int j = 0; j < 8; j++) {
                oacc[j][0] *= al0; oacc[j][1] *= al0;
                oacc[j][2] *= al1; oacc[j][3] *= al1;
            }
            const uint32_t vbase = sb + SM_KV + (kt & 1) * KV_STAGE + 9216;
#pragma unroll
            for (int kb = 0; kb < 2; kb++) {
                uint32_t Aph[4] = {ph[2 * kb], ph2[2 * kb], ph[2 * kb + 1], ph2[2 * kb + 1]};
                const uint32_t vrow = (32 * ch + 16 * kb + lrow) * ASTR;
#pragma unroll
                for (int jj = 0; jj < 4; jj++) {
                    uint32_t vh[4], vl[4];
                    const uint32_t coff = (16 * jj + lcol) * 2;
                    ldmx4t(vh, vbase + vrow + coff);
                    ldmx4t(vl, vbase + 9216 + vrow + coff);
                    mma16816h(oacc[2 * jj],     Aph, make_uint2(vh[0], vh[1]));
                    mma16816h(oacc[2 * jj + 1], Aph, make_uint2(vh[2], vh[3]));
                    mma16816h(oacc[2 * jj],     Aph, make_uint2(vl[0], vl[1]));
                    mma16816h(oacc[2 * jj + 1], Aph, make_uint2(vl[2], vl[3]));
                }
            }
            __syncthreads();   // protect KV stage + redB for next iteration

            l0 = l0 * al0 + redB[r0] + redB[64 + r0];
            l1 = l1 * al1 + redB[r1] + redB[64 + r1];
        }

        // ---- epilogue: reduce O halves across warp pairs, normalize, store ----
        float* ob = (float*)(smem + SM_OB);
        if (ch == 1) {
#pragma unroll
            for (int j = 0; j < 8; j++) {
                *(float2*)(ob + r0 * 68 + 8 * j + 2 * tq) =
                    make_float2(oacc[j][0], oacc[j][1]);
                *(float2*)(ob + r1 * 68 + 8 * j + 2 * tq) =
                    make_float2(oacc[j][2], oacc[j][3]);
            }
        }
        __syncthreads();
        if (ch == 0) {
            const float inv0 = 1.0f / l0;
            const float inv1 = 1.0f / l1;
            float* out0 = Out + ((size_t)b * TT + q0 + r0) * HH;
            float* out1 = Out + ((size_t)b * TT + q0 + r1) * HH;
#pragma unroll
            for (int j = 0; j < 8; j++) {
                float2 p0 = *(float2*)(ob + r0 * 68 + 8 * j + 2 * tq);
                float2 p1 = *(float2*)(ob + r1 * 68 + 8 * j + 2 * tq);
                *(float2*)(out0 + 8 * j + 2 * tq) =
                    make_float2((oacc[j][0] + p0.x) * inv0, (oacc[j][1] + p0.y) * inv0);
                *(float2*)(out1 + 8 * j + 2 * tq) =
                    make_float2((oacc[j][2] + p1.x) * inv1, (oacc[j][3] + p1.y) * inv1);
            }
        }
        __syncthreads();   // smem (Q region, OB) safe before next pi's issues
    }
}

// ---------------------------------------------------------------------------
extern "C" void kernel_launch(void* const* d_in, const int* in_sizes, int n_in,
                              void* d_out, int out_size)
{
    const float* x  = (const float*)d_in[0];
    const float* Wq = (const float*)d_in[1];
    const float* Wk = (const float*)d_in[2];
    const float* Wv = (const float*)d_in[3];
    float* out = (float*)d_out;

    cudaFuncSetAttribute(qkv_mma_kernel,
                         cudaFuncAttributeMaxDynamicSharedMemorySize, QS_TOTAL);
    cudaFuncSetAttribute(attn_kernel,
                         cudaFuncAttributeMaxDynamicSharedMemorySize, ATTN_SMEM);

    wprep_kernel<<<dim3(16, 3), 256>>>(Wq, Wk, Wv);
    qkv_mma_kernel<<<MTOT / 128, 256, QS_TOTAL>>>(x);
    attn_kernel<<<dim3(16, BB), 256, ATTN_SMEM>>>(out);
}

// round 14
// speedup vs baseline: 1.8011x; 1.3233x over previous
#include <cuda_runtime.h>
#include <cuda_fp16.h>
#include <cstdint>

// Problem constants
#define BB   8
#define TT   2048
#define DD   1024
#define HH   64
#define MTOT (BB * TT)   // 16384

// fp16 Q,K,V (single precision fp16; Q pre-scaled 1/8) from the projection.
__device__ __half g_q16[(size_t)MTOT * HH];
__device__ __half g_k16[(size_t)MTOT * HH];
__device__ __half g_v16[(size_t)MTOT * HH];
// fp16 transposed weights (single product projection GEMM)
__device__ __half g_Wt[192 * 1024];

// ===========================================================================
// Helpers (plain sm_100-compatible: mma.sync + cp.async + ldmatrix)
// ===========================================================================
__device__ __forceinline__ uint32_t smem_u32(const void* p) {
    uint32_t a;
    asm("{ .reg .u64 t; cvta.to.shared.u64 t, %1; cvt.u32.u64 %0, t; }"
        : "=r"(a) : "l"(p));
    return a;
}
#define CP_ASYNC16(dst, src) \
    asm volatile("cp.async.cg.shared.global [%0], [%1], 16;" \
                 :: "r"(dst), "l"(src) : "memory")
#define CP_COMMIT() asm volatile("cp.async.commit_group;" ::: "memory")
#define CP_WAIT1()  asm volatile("cp.async.wait_group 1;" ::: "memory")
#define CP_WAIT0()  asm volatile("cp.async.wait_group 0;" ::: "memory")

// fp16 mma, fp32 accumulate
__device__ __forceinline__ void mma16816h(float* c, const uint32_t* a, uint2 b) {
    asm volatile(
        "mma.sync.aligned.m16n8k16.row.col.f32.f16.f16.f32 "
        "{%0,%1,%2,%3}, {%4,%5,%6,%7}, {%8,%9}, {%0,%1,%2,%3};"
        : "+f"(c[0]), "+f"(c[1]), "+f"(c[2]), "+f"(c[3])
        : "r"(a[0]), "r"(a[1]), "r"(a[2]), "r"(a[3]), "r"(b.x), "r"(b.y));
}

__device__ __forceinline__ void ldmx4t(uint32_t* r, uint32_t addr) {
    asm volatile("ldmatrix.sync.aligned.m8n8.x4.trans.shared.b16 "
                 "{%0,%1,%2,%3}, [%4];"
                 : "=r"(r[0]), "=r"(r[1]), "=r"(r[2]), "=r"(r[3]) : "r"(addr));
}

// ===========================================================================
// Kernel 0: W prep — smem-tiled transpose, single fp16 output.
// grid (16, 3): block handles 64 k-rows of one W. In-k16 pair permutation.
// ===========================================================================
__global__ __launch_bounds__(256) void wprep_kernel(
    const float* __restrict__ Wq,
    const float* __restrict__ Wk,
    const float* __restrict__ Wv)
{
    __shared__ float tile[64][65];
    const int g  = blockIdx.y;
    const float* W = (g == 0) ? Wq : ((g == 1) ? Wk : Wv);
    const int k0 = blockIdx.x * 64;

#pragma unroll
    for (int i = 0; i < 16; i++) {
        int idx = threadIdx.x + 256 * i;
        int r = idx >> 6, c = idx & 63;
        tile[r][c] = W[(size_t)(k0 + r) * 64 + c];   // coalesced
    }
    __syncthreads();
#pragma unroll
    for (int i = 0; i < 16; i++) {
        int idx = threadIdx.x + 256 * i;
        int n = idx >> 6, r = idx & 63;
        float w = tile[r][n];                         // stride-65: conflict-free
        int k = k0 + r;
        int p = (k & 15) >> 1;
        int pos = (k & ~15) + (p & 3) * 4 + (p >> 2) * 2 + (k & 1);
        g_Wt[(size_t)(g * 64 + n) * 1024 + pos] = __float2half_rn(w);
    }
}

// ===========================================================================
// Kernel 1: QKV projection — single fp16 product (x16 @ w16).
// C[g][16384,64] = X @ W[g]. Per CTA: 128 rows x 192 cols. K chunks of 64,
// cp.async double-buffered. 8 warps = 4(m,32 rows) x 2(n,96 cols).
// Epilogue emits fp16 q (scaled 1/8), k, v.
// ===========================================================================
#define XS_STRIDE 272
#define WS_STRIDE 144
#define XS_BYTES  (128 * XS_STRIDE)
#define WS_BYTES  (192 * WS_STRIDE)
#define QS_STAGE  (XS_BYTES + WS_BYTES)
#define QS_TOTAL  (2 * QS_STAGE)

__global__ __launch_bounds__(256, 1) void qkv_mma_kernel(const float* __restrict__ X)
{
    extern __shared__ char smem[];
    const uint32_t sb = smem_u32(smem);
    const int tid  = threadIdx.x;
    const int wid  = tid >> 5;
    const int lane = tid & 31;
    const int gid  = lane >> 2;
    const int tq   = lane & 3;
    const int wm   = (wid & 3) * 32;
    const int wn   = (wid >> 2) * 96;

    const char* Xg = (const char*)(X + (size_t)blockIdx.x * 128 * DD);
    const char* Wg = (const char*)g_Wt;

    auto issue = [&](int c, int s) {
        const uint32_t st = sb + s * QS_STAGE;
        const char* xs = Xg + c * 256;
#pragma unroll
        for (int i = 0; i < 8; i++) {
            int u = tid + 256 * i;
            int r = u >> 4, col = u & 15;
            CP_ASYNC16(st + r * XS_STRIDE + col * 16, xs + (size_t)r * 4096 + col * 16);
        }
        const uint32_t wh = st + XS_BYTES;
        const char* whs = Wg + c * 128;
#pragma unroll
        for (int i = 0; i < 6; i++) {
            int u = tid + 256 * i;
            int n = u >> 3, col = u & 7;
            CP_ASYNC16(wh + n * WS_STRIDE + col * 16, whs + (size_t)n * 2048 + col * 16);
        }
        CP_COMMIT();
    };

    float acc[2][12][4];
#pragma unroll
    for (int m = 0; m < 2; m++)
#pragma unroll
        for (int j = 0; j < 12; j++) {
            acc[m][j][0] = 0.f; acc[m][j][1] = 0.f;
            acc[m][j][2] = 0.f; acc[m][j][3] = 0.f;
        }

    issue(0, 0);

    for (int c = 0; c < 16; c++) {
        const int s = c & 1;
        if (c < 15) { issue(c + 1, s ^ 1); CP_WAIT1(); }
        else        { CP_WAIT0(); }
        __syncthreads();

        const char* Xs = smem + s * QS_STAGE;
        const char* Wh = Xs + XS_BYTES;

#pragma unroll
        for (int ks = 0; ks < 4; ks++) {
            // ---- A fragments: load fp32, convert to single fp16 ----
            uint32_t A[2][4];
#pragma unroll
            for (int m = 0; m < 2; m++) {
                const int r0 = wm + m * 16 + gid;
                const char* base = Xs + (size_t)r0 * XS_STRIDE + ks * 64 + tq * 8;
                float2 f0 = *(const float2*)(base);
                float2 f1 = *(const float2*)(base + 8 * XS_STRIDE);
                float2 f2 = *(const float2*)(base + 32);
                float2 f3 = *(const float2*)(base + 8 * XS_STRIDE + 32);
                __half2 h0 = __floats2half2_rn(f0.x, f0.y);
                __half2 h1 = __floats2half2_rn(f1.x, f1.y);
                __half2 h2 = __floats2half2_rn(f2.x, f2.y);
                __half2 h3 = __floats2half2_rn(f3.x, f3.y);
                A[m][0] = *(uint32_t*)&h0;
                A[m][1] = *(uint32_t*)&h1;
                A[m][2] = *(uint32_t*)&h2;
                A[m][3] = *(uint32_t*)&h3;
            }
            // ---- B fragments + single-product MMAs ----
#pragma unroll
            for (int j = 0; j < 12; j++) {
                const size_t boff = (size_t)(wn + j * 8 + gid) * WS_STRIDE + ks * 32 + tq * 8;
                uint2 bh = *(const uint2*)(Wh + boff);
#pragma unroll
                for (int m = 0; m < 2; m++)
                    mma16816h(acc[m][j], A[m], bh);
            }
        }
        __syncthreads();
    }

    // ---- epilogue: fp16 outputs (q scaled 1/8) ----
#pragma unroll
    for (int m = 0; m < 2; m++) {
        const size_t row = (size_t)blockIdx.x * 128 + wm + m * 16 + gid;
#pragma unroll
        for (int j = 0; j < 12; j++) {
            const int nc = wn + j * 8 + tq * 2;
            const int g  = nc >> 6;
            const int cc = nc & 63;
            const float sc = (g == 0) ? 0.125f : 1.0f;
            __half* dst = (g == 0) ? g_q16 : ((g == 1) ? g_k16 : g_v16);
            *(__half2*)(dst + row * HH + cc) =
                __floats2half2_rn(acc[m][j][0] * sc, acc[m][j][1] * sc);
            *(__half2*)(dst + (row + 8) * HH + cc) =
                __floats2half2_rn(acc[m][j][2] * sc, acc[m][j][3] * sc);
        }
    }
}

// ===========================================================================
// Kernel 2: flash attention (causal) — fp16 mma.sync, all single products.
// S = q16 @ k16^T.  PV = P16 @ V16.
// q-tile 64, kv-tile 64, pairing {g, 31-g} -> 33 iters/block, 128 blocks.
// ===========================================================================
#define ASTR      144        // smem tile row stride (64*2 B + 16 pad)
#define SM_Q      0
#define SM_KV     9216
#define KV_STAGE  18432      // K, V at +0, +9216
#define SM_RA     46080      // float[2][64]
#define SM_RB     46592      // float[2][64]
#define SM_OB     9216       // epilogue O buffer (overlaps KV stages)
#define ATTN_SMEM 47104

__global__ __launch_bounds__(256, 1) void attn_kernel(float* __restrict__ Out)
{
    extern __shared__ char smem[];
    const uint32_t sb = smem_u32(smem);

    const int b = blockIdx.y;
    const int g = blockIdx.x;
    const int tid  = threadIdx.x;
    const int wid  = tid >> 5;
    const int lane = tid & 31;
    const int ch   = wid >> 2;     // kv col half (0: 0-31, 1: 32-63)
    const int rg   = wid & 3;      // q row group (16 rows)
    const int gid  = lane >> 2;
    const int tq   = lane & 3;

    const size_t boff = (size_t)b * TT * HH * 2;   // byte offset for this batch
    const char* qg = (const char*)g_q16 + boff;
    const char* kg = (const char*)g_k16 + boff;
    const char* vg = (const char*)g_v16 + boff;

    float* redA = (float*)(smem + SM_RA);
    float* redB = (float*)(smem + SM_RB);

    const int r0 = 16 * rg + gid;       // this thread's q rows (local)
    const int r1 = r0 + 8;

    // ldmatrix lane address components for transposed V loads
    const int lrow = (lane & 7) + ((lane >> 3) & 1) * 8;
    const int lcol = (lane >> 4) * 8;

    // async loaders -------------------------------------------------------
    auto issue_q = [&](int q0) {
#pragma unroll
        for (int i = 0; i < 2; i++) {
            int u = tid + 256 * i;             // 0..511
            int r = u >> 3;
            int cc = u & 7;
            CP_ASYNC16(sb + SM_Q + r * ASTR + cc * 16,
                       qg + (size_t)(q0 + r) * 128 + cc * 16);
        }
        CP_COMMIT();
    };
    auto issue_kv = [&](int k0, int s) {
        const uint32_t base = sb + SM_KV + s * KV_STAGE;
#pragma unroll
        for (int i = 0; i < 4; i++) {
            int u = tid + 256 * i;             // 0..1023
            int t = u >> 9;                    // 0: K, 1: V
            int r = (u >> 3) & 63;
            int cc = u & 7;
            const char* src = (t == 0 ? kg : vg) + (size_t)(k0 + r) * 128 + cc * 16;
            CP_ASYNC16(base + t * 9216 + r * ASTR + cc * 16, src);
        }
        CP_COMMIT();
    };

    for (int pi = 0; pi < 2; pi++) {
        const int qt = pi ? (31 - g) : g;
        const int q0 = qt * 64;

        issue_q(q0);
        issue_kv(0, 0);

        float m0 = -1e30f, m1 = -1e30f, l0 = 0.f, l1 = 0.f;
        float oacc[8][4];
#pragma unroll
        for (int j = 0; j < 8; j++) {
            oacc[j][0] = 0.f; oacc[j][1] = 0.f; oacc[j][2] = 0.f; oacc[j][3] = 0.f;
        }

        for (int kt = 0; kt <= qt; kt++) {
            if (kt < qt) { issue_kv((kt + 1) * 64, (kt + 1) & 1); CP_WAIT1(); }
            else         { CP_WAIT0(); }
            __syncthreads();

            const char* stg = smem + SM_KV + (kt & 1) * KV_STAGE;

            // ---- S = Q @ K^T (single fp16 product) ----
            float sacc[4][4];
#pragma unroll
            for (int j = 0; j < 4; j++) {
                sacc[j][0] = 0.f; sacc[j][1] = 0.f; sacc[j][2] = 0.f; sacc[j][3] = 0.f;
            }
            {
                const char* qh = smem + SM_Q + r0 * ASTR + tq * 4;
                const char* kh = stg + (32 * ch + gid) * ASTR + tq * 4;
#pragma unroll
                for (int kb = 0; kb < 4; kb++) {
                    uint32_t A[4];
                    A[0] = *(const uint32_t*)(qh + kb * 32);
                    A[1] = *(const uint32_t*)(qh + 8 * ASTR + kb * 32);
                    A[2] = *(const uint32_t*)(qh + kb * 32 + 16);
                    A[3] = *(const uint32_t*)(qh + 8 * ASTR + kb * 32 + 16);
#pragma unroll
                    for (int j = 0; j < 4; j++) {
                        uint2 bh;
                        bh.x = *(const uint32_t*)(kh + j * 8 * ASTR + kb * 32);
                        bh.y = *(const uint32_t*)(kh + j * 8 * ASTR + kb * 32 + 16);
                        mma16816h(sacc[j], A, bh);
                    }
                }
            }

            // ---- causal mask + partial row max ----
            const bool diag = (kt == qt);
            float mx0 = -1e30f, mx1 = -1e30f;
#pragma unroll
            for (int j = 0; j < 4; j++) {
                const int c0 = 32 * ch + 8 * j + 2 * tq;
                if (diag) {
                    if (c0     > r0) sacc[j][0] = -1e30f;
                    if (c0 + 1 > r0) sacc[j][1] = -1e30f;
                    if (c0     > r1) sacc[j][2] = -1e30f;
                    if (c0 + 1 > r1) sacc[j][3] = -1e30f;
                }
                mx0 = fmaxf(mx0, fmaxf(sacc[j][0], sacc[j][1]));
                mx1 = fmaxf(mx1, fmaxf(sacc[j][2], sacc[j][3]));
            }
            mx0 = fmaxf(mx0, __shfl_xor_sync(0xffffffffu, mx0, 1));
            mx0 = fmaxf(mx0, __shfl_xor_sync(0xffffffffu, mx0, 2));
            mx1 = fmaxf(mx1, __shfl_xor_sync(0xffffffffu, mx1, 1));
            mx1 = fmaxf(mx1, __shfl_xor_sync(0xffffffffu, mx1, 2));
            if (tq == 0) {
                redA[ch * 64 + r0] = mx0;
                redA[ch * 64 + r1] = mx1;
            }
            __syncthreads();

            // ---- full row max, exp, partial sums ----
            const float om0 = m0, om1 = m1;
            m0 = fmaxf(m0, fmaxf(redA[r0], redA[64 + r0]));
            m1 = fmaxf(m1, fmaxf(redA[r1], redA[64 + r1]));
            const float al0 = __expf(om0 - m0);
            const float al1 = __expf(om1 - m1);
            float s0 = 0.f, s1 = 0.f;
#pragma unroll
            for (int j = 0; j < 4; j++) {
                sacc[j][0] = __expf(sacc[j][0] - m0);
                sacc[j][1] = __expf(sacc[j][1] - m0);
                sacc[j][2] = __expf(sacc[j][2] - m1);
                sacc[j][3] = __expf(sacc[j][3] - m1);
                s0 += sacc[j][0] + sacc[j][1];
                s1 += sacc[j][2] + sacc[j][3];
            }
            s0 += __shfl_xor_sync(0xffffffffu, s0, 1);
            s0 += __shfl_xor_sync(0xffffffffu, s0, 2);
            s1 += __shfl_xor_sync(0xffffffffu, s1, 1);
            s1 += __shfl_xor_sync(0xffffffffu, s1, 2);
            if (tq == 0) {
                redB[ch * 64 + r0] = s0;
                redB[ch * 64 + r1] = s1;
            }

            // ---- pack P to single fp16 (registers only) ----
            uint32_t ph[4], ph2[4];
#pragma unroll
            for (int j = 0; j < 4; j++) {
                __half2 t0 = __floats2half2_rn(sacc[j][0], sacc[j][1]);
                __half2 t1 = __floats2half2_rn(sacc[j][2], sacc[j][3]);
                ph[j]  = *(uint32_t*)&t0;
                ph2[j] = *(uint32_t*)&t1;
            }

            // ---- rescale O, then O += P @ V (single product) ----
#pragma unroll
            for (int j = 0; j < 8; j++) {
                oacc[j][0] *= al0; oacc[j][1] *= al0;
                oacc[j][2] *= al1; oacc[j][3] *= al1;
            }
            const uint32_t vbase = sb + SM_KV + (kt & 1) * KV_STAGE + 9216;
#pragma unroll
            for (int kb = 0; kb < 2; kb++) {
                uint32_t Aph[4] = {ph[2 * kb], ph2[2 * kb], ph[2 * kb + 1], ph2[2 * kb + 1]};
                const uint32_t vrow = (32 * ch + 16 * kb + lrow) * ASTR;
#pragma unroll
                for (int jj = 0; jj < 4; jj++) {
                    uint32_t vh[4];
                    ldmx4t(vh, vbase + vrow + (16 * jj + lcol) * 2);
                    mma16816h(oacc[2 * jj],     Aph, make_uint2(vh[0], vh[1]));
                    mma16816h(oacc[2 * jj + 1], Aph, make_uint2(vh[2], vh[3]));
                }
            }
            __syncthreads();   // protect KV stage + redB for next iteration

            l0 = l0 * al0 + redB[r0] + redB[64 + r0];
            l1 = l1 * al1 + redB[r1] + redB[64 + r1];
        }

        // ---- epilogue: reduce O halves across warp pairs, normalize, store ----
        float* ob = (float*)(smem + SM_OB);
        if (ch == 1) {
#pragma unroll
            for (int j = 0; j < 8; j++) {
                *(float2*)(ob + r0 * 68 + 8 * j + 2 * tq) =
                    make_float2(oacc[j][0], oacc[j][1]);
                *(float2*)(ob + r1 * 68 + 8 * j + 2 * tq) =
                    make_float2(oacc[j][2], oacc[j][3]);
            }
        }
        __syncthreads();
        if (ch == 0) {
            const float inv0 = 1.0f / l0;
            const float inv1 = 1.0f / l1;
            float* out0 = Out + ((size_t)b * TT + q0 + r0) * HH;
            float* out1 = Out + ((size_t)b * TT + q0 + r1) * HH;
#pragma unroll
            for (int j = 0; j < 8; j++) {
                float2 p0 = *(float2*)(ob + r0 * 68 + 8 * j + 2 * tq);
                float2 p1 = *(float2*)(ob + r1 * 68 + 8 * j + 2 * tq);
                *(float2*)(out0 + 8 * j + 2 * tq) =
                    make_float2((oacc[j][0] + p0.x) * inv0, (oacc[j][1] + p0.y) * inv0);
                *(float2*)(out1 + 8 * j + 2 * tq) =
                    make_float2((oacc[j][2] + p1.x) * inv1, (oacc[j][3] + p1.y) * inv1);
            }
        }
        __syncthreads();   // smem (Q region, OB) safe before next pi's issues
    }
}

// ---------------------------------------------------------------------------
extern "C" void kernel_launch(void* const* d_in, const int* in_sizes, int n_in,
                              void* d_out, int out_size)
{
    const float* x  = (const float*)d_in[0];
    const float* Wq = (const float*)d_in[1];
    const float* Wk = (const float*)d_in[2];
    const float* Wv = (const float*)d_in[3];
    float* out = (float*)d_out;

    cudaFuncSetAttribute(qkv_mma_kernel,
                         cudaFuncAttributeMaxDynamicSharedMemorySize, QS_TOTAL);
    cudaFuncSetAttribute(attn_kernel,
                         cudaFuncAttributeMaxDynamicSharedMemorySize, ATTN_SMEM);

    wprep_kernel<<<dim3(16, 3), 256>>>(Wq, Wk, Wv);
    qkv_mma_kernel<<<MTOT / 128, 256, QS_TOTAL>>>(x);
    attn_kernel<<<dim3(16, BB), 256, ATTN_SMEM>>>(out);
}